// round 15
// baseline (speedup 1.0000x reference)
#include <cuda_runtime.h>
#include <math.h>

// ---------------- problem constants ----------------
constexpr int kB    = 16;
constexpr int kL    = 64;
constexpr int kD    = 256;
constexpr int kDIN  = 512;
constexpr int kH    = 8;
constexpr int kDH   = 64;
constexpr int kN    = 64;
constexpr int kCDIM = 640;
constexpr int kP    = 1160;
constexpr int kPF   = 768;
constexpr int kCLS  = 1000;
constexpr float kEPS = 1e-6f;
constexpr int kTOK  = kB * kL;  // 1024

// GEMM smem geometry (floats)
constexpr int kAStride = 36;
constexpr int kAStage  = 64 * kAStride;      // 2304
constexpr int kBBase   = 2 * kAStage;        // 4608

// attn kernel smem layout (floats) — compact: one 64x68 staging buffer
constexpr int aST  = 0;          // staging 64*68 (reused X, B, C passes)
constexpr int aXT  = 4352;       // X transposed [p][s'] 64*68
constexpr int aBm  = 8704;       // B [s'][n] 64*68
constexpr int aCm  = 13056;      // C [s][n] 64*68; reused as W [s][s']
constexpr int aDT  = 17408;      // 64
constexpr int aCUM = 17472;      // 64
constexpr int kAttnSmemBytes = 17536 * 4;    // 70144 -> 3 blocks/SM

// ---------------- scratch ----------------
__device__ float g_t[kTOK*kD];
__device__ float g_nx[kTOK*kD];
__device__ float g_zx[2][kTOK*kP];
__device__ float g_y[2][kTOK*kDIN];
__device__ float g_o[2][kTOK*kD];

// ---------------- helpers ----------------
__device__ __forceinline__ int snake_src(int l) {
    int r = l >> 3, c = l & 7;
    return r * 8 + ((r & 1) ? (7 - c) : c);
}

__device__ __forceinline__ float warp_sum(float v) {
    #pragma unroll
    for (int o = 16; o > 0; o >>= 1) v += __shfl_xor_sync(0xffffffffu, v, o);
    return v;
}

__device__ __forceinline__ float siluf(float x) {
    return x / (1.f + expf(-x));
}

__device__ __forceinline__ unsigned f2tf32(float f) {
    unsigned r;
    asm("cvt.rna.tf32.f32 %0, %1;" : "=r"(r) : "f"(f));
    return r;
}

__device__ __forceinline__ void cpa16(float* dst, const float* src) {
    unsigned d = (unsigned)__cvta_generic_to_shared(dst);
    asm volatile("cp.async.cg.shared.global [%0], [%1], 16;" :: "r"(d), "l"(src));
}

__device__ __forceinline__ void mma_tf32(float c[4], const unsigned a[4],
                                         unsigned b0, unsigned b1) {
    asm volatile(
        "mma.sync.aligned.m16n8k8.row.col.f32.tf32.tf32.f32 "
        "{%0,%1,%2,%3}, {%4,%5,%6,%7}, {%8,%9}, {%0,%1,%2,%3};"
        : "+f"(c[0]), "+f"(c[1]), "+f"(c[2]), "+f"(c[3])
        : "r"(a[0]), "r"(a[1]), "r"(a[2]), "r"(a[3]), "r"(b0), "r"(b1));
}

// ---------------- kernels ----------------

// ---- patch GEMM: 64x64 tiles (fused patchify + transpose-B + bias + pos) ----
__global__ void __launch_bounds__(256) k_gemm_patch(
        const float* __restrict__ x, const float* __restrict__ Bw,
        const float* __restrict__ pb, const float* __restrict__ pos,
        float* __restrict__ C) {
    __shared__ unsigned As[16][72];
    __shared__ unsigned Bs[16][72];
    int tid = threadIdx.x;
    int lane = tid & 31, warp = tid >> 5;
    int lg = lane >> 2, lt = lane & 3;
    int wm = (warp >> 2) * 32;
    int wn = (warp & 3) * 16;
    int m0 = blockIdx.y * 64, n0 = blockIdx.x * 64;

    float c[2][2][4];
    #pragma unroll
    for (int a = 0; a < 2; a++)
        #pragma unroll
        for (int b = 0; b < 2; b++)
            #pragma unroll
            for (int d = 0; d < 4; d++) c[a][b][d] = 0.f;

    int am = tid >> 2;
    int ak = (tid & 3) * 4;
    int bk = tid >> 4;
    int bn = (tid & 15) * 4;

    int m = m0 + am;
    int bimg = m >> 6, l = m & 63;
    int src = snake_src(l);
    int gr = src >> 3, gc = src & 7;

    for (int k0 = 0; k0 < kPF; k0 += 16) {
        {
            int f = k0 + ak;
            int ch = f >> 8, rem = f & 255;
            int pr = rem >> 4, pc = rem & 15;
            const float* ap = x + ((long)(bimg * 3 + ch) * 128 + gr * 16 + pr) * 128
                                + gc * 16 + pc;
            float4 v = *(const float4*)(ap);
            As[ak + 0][am] = f2tf32(v.x);
            As[ak + 1][am] = f2tf32(v.y);
            As[ak + 2][am] = f2tf32(v.z);
            As[ak + 3][am] = f2tf32(v.w);
        }
        {
            #pragma unroll
            for (int j = 0; j < 4; j++)
                Bs[bk][bn + j] = f2tf32(Bw[(long)(n0 + bn + j) * kPF + k0 + bk]);
        }
        __syncthreads();
        #pragma unroll
        for (int k8 = 0; k8 < 16; k8 += 8) {
            unsigned afr[2][4], bfr[2][2];
            #pragma unroll
            for (int mt = 0; mt < 2; mt++) {
                int mb = wm + mt * 16;
                afr[mt][0] = As[k8 + lt][mb + lg];
                afr[mt][1] = As[k8 + lt][mb + 8 + lg];
                afr[mt][2] = As[k8 + lt + 4][mb + lg];
                afr[mt][3] = As[k8 + lt + 4][mb + 8 + lg];
            }
            #pragma unroll
            for (int nt = 0; nt < 2; nt++) {
                bfr[nt][0] = Bs[k8 + lt][wn + nt * 8 + lg];
                bfr[nt][1] = Bs[k8 + lt + 4][wn + nt * 8 + lg];
            }
            #pragma unroll
            for (int mt = 0; mt < 2; mt++)
                #pragma unroll
                for (int nt = 0; nt < 2; nt++)
                    mma_tf32(c[mt][nt], afr[mt], bfr[nt][0], bfr[nt][1]);
        }
        __syncthreads();
    }

    #pragma unroll
    for (int mt = 0; mt < 2; mt++) {
        int r0 = m0 + wm + mt * 16 + lg;
        int l0 = r0 & 63, l8 = (r0 + 8) & 63;
        int s0 = snake_src(l0) * kD, s8 = snake_src(l8) * kD;
        #pragma unroll
        for (int nt = 0; nt < 2; nt++) {
            int gn = n0 + wn + nt * 8 + 2 * lt;
            C[(long)r0 * kD + gn]           = c[mt][nt][0] + pb[gn] + pos[s0 + gn];
            C[(long)r0 * kD + gn + 1]       = c[mt][nt][1] + pb[gn + 1] + pos[s0 + gn + 1];
            C[(long)(r0 + 8) * kD + gn]     = c[mt][nt][2] + pb[gn] + pos[s8 + gn];
            C[(long)(r0 + 8) * kD + gn + 1] = c[mt][nt][3] + pb[gn + 1] + pos[s8 + gn + 1];
        }
    }
}

// ---- TF32 GEMM, cp.async double-buffered, K-step 32, M-tile 64, N-tile 64 ----
__global__ void __launch_bounds__(256) k_gemm_tc(
        const float* __restrict__ Abase,
        const float* __restrict__ B0, const float* __restrict__ B1,
        float* __restrict__ Cbase,
        int M, int N, int K, long sA, long sC) {
    extern __shared__ float smem[];
    constexpr int BStride = 72;
    constexpr int BStage = 32 * BStride;
    int z = blockIdx.z;
    const float* A = Abase + (long)z * sA;
    const float* B = z ? B1 : B0;
    float* C = Cbase + (long)z * sC;
    int tid = threadIdx.x;
    int lane = tid & 31, warp = tid >> 5;
    int lg = lane >> 2, lt = lane & 3;
    int wm = (warp >> 2) * 32;
    int wn = (warp & 3) * 16;
    int m0 = blockIdx.y * 64, n0 = blockIdx.x * 64;

    float c[2][2][4];
    #pragma unroll
    for (int a = 0; a < 2; a++)
        #pragma unroll
        for (int b = 0; b < 2; b++)
            #pragma unroll
            for (int d = 0; d < 4; d++) c[a][b][d] = 0.f;

    int am = tid >> 2, ak = (tid & 3) * 8;
    int bk = tid >> 3, bn = (tid & 7) * 8;

    if (n0 + 64 > N) {
        for (int i = tid; i < 2 * BStage; i += 256) smem[kBBase + i] = 0.f;
        __syncthreads();
    }

    int nIters = K >> 5;

    {
        const float* ap = A + (long)(m0 + am) * K + ak;
        float* ad = &smem[am * kAStride + ak];
        cpa16(ad, ap); cpa16(ad + 4, ap + 4);
        const float* bp = B + (long)bk * N + n0 + bn;
        float* bd = &smem[kBBase + bk * BStride + bn];
        if (n0 + bn < N) cpa16(bd, bp);
        if (n0 + bn + 4 < N) cpa16(bd + 4, bp + 4);
        asm volatile("cp.async.commit_group;");
    }

    for (int it = 0; it < nIters; it++) {
        if (it + 1 < nIters) {
            int k0 = (it + 1) << 5;
            int st = (it + 1) & 1;
            const float* ap = A + (long)(m0 + am) * K + k0 + ak;
            float* ad = &smem[st * kAStage + am * kAStride + ak];
            cpa16(ad, ap); cpa16(ad + 4, ap + 4);
            const float* bp = B + (long)(k0 + bk) * N + n0 + bn;
            float* bd = &smem[kBBase + st * BStage + bk * BStride + bn];
            if (n0 + bn < N) cpa16(bd, bp);
            if (n0 + bn + 4 < N) cpa16(bd + 4, bp + 4);
            asm volatile("cp.async.commit_group;");
            asm volatile("cp.async.wait_group 1;");
        } else {
            asm volatile("cp.async.wait_group 0;");
        }
        __syncthreads();

        const float* Ab = &smem[(it & 1) * kAStage];
        const float* Bb = &smem[kBBase + (it & 1) * BStage];
        #pragma unroll
        for (int k8 = 0; k8 < 32; k8 += 8) {
            unsigned afr[2][4], bfr[2][2];
            #pragma unroll
            for (int mt = 0; mt < 2; mt++) {
                int mb = wm + mt * 16;
                afr[mt][0] = f2tf32(Ab[(mb + lg) * kAStride + k8 + lt]);
                afr[mt][1] = f2tf32(Ab[(mb + 8 + lg) * kAStride + k8 + lt]);
                afr[mt][2] = f2tf32(Ab[(mb + lg) * kAStride + k8 + lt + 4]);
                afr[mt][3] = f2tf32(Ab[(mb + 8 + lg) * kAStride + k8 + lt + 4]);
            }
            #pragma unroll
            for (int nt = 0; nt < 2; nt++) {
                bfr[nt][0] = f2tf32(Bb[(k8 + lt) * BStride + wn + nt * 8 + lg]);
                bfr[nt][1] = f2tf32(Bb[(k8 + lt + 4) * BStride + wn + nt * 8 + lg]);
            }
            #pragma unroll
            for (int mt = 0; mt < 2; mt++)
                #pragma unroll
                for (int nt = 0; nt < 2; nt++)
                    mma_tf32(c[mt][nt], afr[mt], bfr[nt][0], bfr[nt][1]);
        }
        __syncthreads();
    }

    #pragma unroll
    for (int mt = 0; mt < 2; mt++) {
        int r0 = m0 + wm + mt * 16 + lg;
        #pragma unroll
        for (int nt = 0; nt < 2; nt++) {
            int gn = n0 + wn + nt * 8 + 2 * lt;
            if (gn < N) {
                C[(long)r0 * N + gn] = c[mt][nt][0];
                C[(long)(r0 + 8) * N + gn] = c[mt][nt][2];
                if (gn + 1 < N) {
                    C[(long)r0 * N + gn + 1] = c[mt][nt][1];
                    C[(long)(r0 + 8) * N + gn + 1] = c[mt][nt][3];
                }
            }
        }
    }
}

// ---- fused residual + rmsnorm; warp-per-row (8 rows / 256-thread block) ----
__global__ void __launch_bounds__(256) k_resnorm(
        float* __restrict__ t, const float* __restrict__ o0,
        const float* __restrict__ o1, const float* __restrict__ w,
        float* __restrict__ nx, int addRes) {
    int warp = threadIdx.x >> 5, lane = threadIdx.x & 31;
    int row = blockIdx.x * 8 + warp;
    long base = (long)row * kD;
    int d0 = lane * 4, d1 = d0 + 128;
    float4 v0 = *(float4*)&t[base + d0];
    float4 v1 = *(float4*)&t[base + d1];
    if (addRes) {
        float4 a0 = *(const float4*)&o0[base + d0];
        float4 a1 = *(const float4*)&o0[base + d1];
        float4 b0 = *(const float4*)&o1[base + d0];
        float4 b1 = *(const float4*)&o1[base + d1];
        v0.x += 0.5f * (a0.x + b0.x); v0.y += 0.5f * (a0.y + b0.y);
        v0.z += 0.5f * (a0.z + b0.z); v0.w += 0.5f * (a0.w + b0.w);
        v1.x += 0.5f * (a1.x + b1.x); v1.y += 0.5f * (a1.y + b1.y);
        v1.z += 0.5f * (a1.z + b1.z); v1.w += 0.5f * (a1.w + b1.w);
        *(float4*)&t[base + d0] = v0;
        *(float4*)&t[base + d1] = v1;
    }
    float ss = v0.x * v0.x + v0.y * v0.y + v0.z * v0.z + v0.w * v0.w
             + v1.x * v1.x + v1.y * v1.y + v1.z * v1.z + v1.w * v1.w;
    ss = warp_sum(ss);
    float sc = rsqrtf(ss * (1.f / kD) + kEPS);
    float4 w0 = *(const float4*)&w[d0];
    float4 w1 = *(const float4*)&w[d1];
    float4 r0 = make_float4(v0.x * sc * w0.x, v0.y * sc * w0.y,
                            v0.z * sc * w0.z, v0.w * sc * w0.w);
    float4 r1 = make_float4(v1.x * sc * w1.x, v1.y * sc * w1.y,
                            v1.z * sc * w1.z, v1.w * sc * w1.w);
    *(float4*)&nx[base + d0] = r0;
    *(float4*)&nx[base + d1] = r1;
}

// ---- dual-form scan on tensor cores: strip-conv + dt + (G=C·Bᵀ, mask, Y=W·X) ----
// grid (kB, kH, 2), 512 threads; compact smem (70.1 KB) -> 3 blocks/SM.
__global__ void __launch_bounds__(512) k_attn(
        const float* __restrict__ zxbase,
        const float* __restrict__ cw0, const float* __restrict__ cw1,
        const float* __restrict__ cb0, const float* __restrict__ cb1,
        const float* __restrict__ dtb0, const float* __restrict__ dtb1,
        const float* __restrict__ Alog0, const float* __restrict__ Alog1,
        const float* __restrict__ Dp0, const float* __restrict__ Dp1,
        float* __restrict__ ybase) {
    extern __shared__ float sm[];
    int b = blockIdx.x, h = blockIdx.y, dir = blockIdx.z;
    const float* zx = zxbase + (long)dir * kTOK * kP;
    float* y        = ybase  + (long)dir * kTOK * kDIN;
    const float* cw  = dir ? cw1 : cw0;
    const float* cb  = dir ? cb1 : cb0;
    float a = -expf((dir ? Alog1 : Alog0)[h]);
    float dpar = (dir ? Dp1 : Dp0)[h];
    float dtbv = (dir ? dtb1 : dtb0)[h];
    int tid = threadIdx.x;
    int nthr = blockDim.x;   // 512

    // ---- pass X: stage (stride 68) + dt softplus; then cumsum (warp0) + strip conv ----
    {
        int off = h * kDH;
        for (int idx = tid; idx < 1024; idx += nthr) {
            int s = idx >> 4, q = (idx & 15) * 4;
            int tok = dir ? (kL - 1 - s) : s;
            float4 v = *(const float4*)&zx[(long)(b * kL + tok) * kP + kDIN + off + q];
            *(float4*)&sm[aST + s * 68 + q] = v;
        }
        if (tid < 64) {
            int s = tid;
            int tok = dir ? (kL - 1 - s) : s;
            float v = zx[(long)(b * kL + tok) * kP + 2 * kDIN + 2 * kN + h] + dtbv;
            sm[aDT + s] = (v > 20.f) ? v : log1pf(expf(v));
        }
        __syncthreads();
        if (tid < 32) {
            float d0 = sm[aDT + 2 * tid], d1 = sm[aDT + 2 * tid + 1];
            float p = d0 + d1;
            #pragma unroll
            for (int o = 1; o < 32; o <<= 1) {
                float t = __shfl_up_sync(0xffffffffu, p, o);
                if (tid >= o) p += t;
            }
            sm[aCUM + 2 * tid] = p - d1;
            sm[aCUM + 2 * tid + 1] = p;
        }
        {
            int cc = tid & 63, strip = tid >> 6;     // 64 ch x 8 strips
            int s0 = strip * 8;
            int ch = off + cc;
            float w0 = cw[ch * 4 + 0], w1 = cw[ch * 4 + 1];
            float w2 = cw[ch * 4 + 2], w3 = cw[ch * 4 + 3];
            float bias = cb[ch];
            float p1 = (s0 >= 1) ? sm[aST + (s0 - 1) * 68 + cc] : 0.f;
            float p2 = (s0 >= 2) ? sm[aST + (s0 - 2) * 68 + cc] : 0.f;
            float p3 = (s0 >= 3) ? sm[aST + (s0 - 3) * 68 + cc] : 0.f;
            #pragma unroll
            for (int j = 0; j < 8; j++) {
                int s = s0 + j;
                float v = sm[aST + s * 68 + cc];
                float acc = bias + w0 * p3 + w1 * p2 + w2 * p1 + w3 * v;
                sm[aXT + cc * 68 + s] = siluf(acc);
                p3 = p2; p2 = p1; p1 = v;
            }
        }
        __syncthreads();
    }

    // ---- pass B then pass C: stage 64 ch (stride 68), strip conv ----
    #pragma unroll
    for (int seg = 0; seg < 2; seg++) {
        int off = kDIN + seg * kN;               // 512 or 576 within xBC space? (abs: zx+kDIN+off)
        for (int idx = tid; idx < 1024; idx += nthr) {
            int s = idx >> 4, q = (idx & 15) * 4;
            int tok = dir ? (kL - 1 - s) : s;
            float4 v = *(const float4*)&zx[(long)(b * kL + tok) * kP + kDIN + off + q];
            *(float4*)&sm[aST + s * 68 + q] = v;
        }
        __syncthreads();
        {
            int cc = tid & 63, strip = tid >> 6;
            int s0 = strip * 8;
            int ch = off + cc;
            float w0 = cw[ch * 4 + 0], w1 = cw[ch * 4 + 1];
            float w2 = cw[ch * 4 + 2], w3 = cw[ch * 4 + 3];
            float bias = cb[ch];
            float p1 = (s0 >= 1) ? sm[aST + (s0 - 1) * 68 + cc] : 0.f;
            float p2 = (s0 >= 2) ? sm[aST + (s0 - 2) * 68 + cc] : 0.f;
            float p3 = (s0 >= 3) ? sm[aST + (s0 - 3) * 68 + cc] : 0.f;
            int dbase = (seg == 0) ? (aBm + cc) : (aCm + cc);
            #pragma unroll
            for (int j = 0; j < 8; j++) {
                int s = s0 + j;
                float v = sm[aST + s * 68 + cc];
                float acc = bias + w0 * p3 + w1 * p2 + w2 * p1 + w3 * v;
                sm[dbase + s * 68] = siluf(acc);
                p3 = p2; p2 = p1; p1 = v;
            }
        }
        __syncthreads();
    }

    int warp = tid >> 5, lane = tid & 31;
    int lg = lane >> 2, lt = lane & 3;
    int mw = (warp >> 2) * 16;       // s rows
    int nw = (warp & 3) * 16;        // sp / p cols

    // ---- phase 1: G = C @ B^T via tf32 MMA ----
    float g[2][4];
    #pragma unroll
    for (int nt = 0; nt < 2; nt++)
        #pragma unroll
        for (int d = 0; d < 4; d++) g[nt][d] = 0.f;
    #pragma unroll
    for (int k0 = 0; k0 < 64; k0 += 8) {
        unsigned af[4];
        af[0] = f2tf32(sm[aCm + (mw + lg) * 68 + k0 + lt]);
        af[1] = f2tf32(sm[aCm + (mw + 8 + lg) * 68 + k0 + lt]);
        af[2] = f2tf32(sm[aCm + (mw + lg) * 68 + k0 + lt + 4]);
        af[3] = f2tf32(sm[aCm + (mw + 8 + lg) * 68 + k0 + lt + 4]);
        #pragma unroll
        for (int nt = 0; nt < 2; nt++) {
            unsigned b0 = f2tf32(sm[aBm + (nw + nt * 8 + lg) * 68 + k0 + lt]);
            unsigned b1 = f2tf32(sm[aBm + (nw + nt * 8 + lg) * 68 + k0 + lt + 4]);
            mma_tf32(g[nt], af, b0, b1);
        }
    }
    __syncthreads();   // all C/B reads done; aCm can be overwritten with W

    // mask + store W into aCm [s][sp]
    {
        int s0 = mw + lg, s8 = mw + 8 + lg;
        float cum0 = sm[aCUM + s0], cum8 = sm[aCUM + s8];
        #pragma unroll
        for (int nt = 0; nt < 2; nt++) {
            int sp = nw + nt * 8 + 2 * lt;
            float csp0 = sm[aCUM + sp], csp1 = sm[aCUM + sp + 1];
            float dt0 = sm[aDT + sp], dt1 = sm[aDT + sp + 1];
            sm[aCm + s0 * 68 + sp]     = (sp     <= s0) ? g[nt][0] * __expf(a * (cum0 - csp0)) * dt0 : 0.f;
            sm[aCm + s0 * 68 + sp + 1] = (sp + 1 <= s0) ? g[nt][1] * __expf(a * (cum0 - csp1)) * dt1 : 0.f;
            sm[aCm + s8 * 68 + sp]     = (sp     <= s8) ? g[nt][2] * __expf(a * (cum8 - csp0)) * dt0 : 0.f;
            sm[aCm + s8 * 68 + sp + 1] = (sp + 1 <= s8) ? g[nt][3] * __expf(a * (cum8 - csp1)) * dt1 : 0.f;
        }
    }
    __syncthreads();

    // ---- phase 2: Y = W @ X via tf32 MMA (A = W[s][sp], B-op = XT[p][sp]) ----
    float yv[2][4];
    #pragma unroll
    for (int nt = 0; nt < 2; nt++)
        #pragma unroll
        for (int d = 0; d < 4; d++) yv[nt][d] = 0.f;
    #pragma unroll
    for (int k0 = 0; k0 < 64; k0 += 8) {
        unsigned af[4];
        af[0] = f2tf32(sm[aCm + (mw + lg) * 68 + k0 + lt]);
        af[1] = f2tf32(sm[aCm + (mw + 8 + lg) * 68 + k0 + lt]);
        af[2] = f2tf32(sm[aCm + (mw + lg) * 68 + k0 + lt + 4]);
        af[3] = f2tf32(sm[aCm + (mw + 8 + lg) * 68 + k0 + lt + 4]);
        #pragma unroll
        for (int nt = 0; nt < 2; nt++) {
            unsigned b0 = f2tf32(sm[aXT + (nw + nt * 8 + lg) * 68 + k0 + lt]);
            unsigned b1 = f2tf32(sm[aXT + (nw + nt * 8 + lg) * 68 + k0 + lt + 4]);
            mma_tf32(yv[nt], af, b0, b1);
        }
    }

    // epilogue: + D*x, write token-order (float2 pairs)
    {
        int s0 = mw + lg, s8 = mw + 8 + lg;
        int tok0 = dir ? (kL - 1 - s0) : s0;
        int tok8 = dir ? (kL - 1 - s8) : s8;
        #pragma unroll
        for (int nt = 0; nt < 2; nt++) {
            int p0 = nw + nt * 8 + 2 * lt;
            float x00 = sm[aXT + p0 * 68 + s0];
            float x01 = sm[aXT + (p0 + 1) * 68 + s0];
            float x80 = sm[aXT + p0 * 68 + s8];
            float x81 = sm[aXT + (p0 + 1) * 68 + s8];
            float2 o0 = make_float2(yv[nt][0] + dpar * x00, yv[nt][1] + dpar * x01);
            float2 o8 = make_float2(yv[nt][2] + dpar * x80, yv[nt][3] + dpar * x81);
            *(float2*)&y[(long)(b * kL + tok0) * kDIN + h * kDH + p0] = o0;
            *(float2*)&y[(long)(b * kL + tok8) * kDIN + h * kDH + p0] = o8;
        }
    }
}

// ---- gate + rmsnorm over DIN; warp-per-row (8 rows / block), both dirs ----
__global__ void __launch_bounds__(256) k_gate_norm2(
        const float* __restrict__ zxbase,
        const float* __restrict__ gn0, const float* __restrict__ gn1,
        float* __restrict__ ybase) {
    int warp = threadIdx.x >> 5, lane = threadIdx.x & 31;
    int row = blockIdx.x * 8 + warp;          // 0..2*kTOK-1
    const float* gn = (row >= kTOK) ? gn1 : gn0;
    const float* zrow = zxbase + (long)row * kP;
    float* yrow = ybase + (long)row * kDIN;
    float4 v[4];
    float ss = 0.f;
    #pragma unroll
    for (int q = 0; q < 4; q++) {
        int d = lane * 4 + q * 128;
        float4 yv = *(const float4*)&yrow[d];
        float4 zv = *(const float4*)&zrow[d];
        v[q].x = yv.x * siluf(zv.x);
        v[q].y = yv.y * siluf(zv.y);
        v[q].z = yv.z * siluf(zv.z);
        v[q].w = yv.w * siluf(zv.w);
        ss += v[q].x * v[q].x + v[q].y * v[q].y + v[q].z * v[q].z + v[q].w * v[q].w;
    }
    ss = warp_sum(ss);
    float sc = rsqrtf(ss * (1.f / kDIN) + kEPS);
    #pragma unroll
    for (int q = 0; q < 4; q++) {
        int d = lane * 4 + q * 128;
        float4 gv = *(const float4*)&gn[d];
        float4 o = make_float4(v[q].x * sc * gv.x, v[q].y * sc * gv.y,
                               v[q].z * sc * gv.z, v[q].w * sc * gv.w);
        *(float4*)&yrow[d] = o;
    }
}

// ---- fused mean-pool + classifier head; grid (kB, 5), 200 classes/block ----
__global__ void k_meanhead(const float* __restrict__ nx, const float* __restrict__ hw,
                           const float* __restrict__ hb, float* __restrict__ out) {
    int b = blockIdx.x;
    int c0 = blockIdx.y * 200;
    int t = threadIdx.x;
    __shared__ float pool[kD];
    float s = 0.f;
    #pragma unroll 8
    for (int l = 0; l < kL; l++) s += nx[(long)(b * kL + l) * kD + t];
    pool[t] = s * (1.f / kL);
    __syncthreads();
    for (int n = c0 + t; n < c0 + 200 && n < kCLS; n += 256) {
        float acc = hb[n];
        #pragma unroll 8
        for (int k = 0; k < kD; k++) acc += pool[k] * hw[(long)k * kCLS + n];
        out[(long)b * kCLS + n] = acc;
    }
}

// ---------------- launch ----------------
extern "C" void kernel_launch(void* const* d_in, const int* in_sizes, int n_in,
                              void* d_out, int out_size) {
    const float* x       = (const float*)d_in[0];
    const float* patch_w = (const float*)d_in[1];
    const float* patch_b = (const float*)d_in[2];
    const float* pos     = (const float*)d_in[3];
    const float* norms_w = (const float*)d_in[4];
    const float* final_w = (const float*)d_in[5];
    const float* head_w  = (const float*)d_in[6];
    const float* head_b  = (const float*)d_in[7];
    const float* Win[2]  = {(const float*)d_in[8],  (const float*)d_in[16]};
    const float* cw[2]   = {(const float*)d_in[9],  (const float*)d_in[17]};
    const float* cb[2]   = {(const float*)d_in[10], (const float*)d_in[18]};
    const float* dtb[2]  = {(const float*)d_in[11], (const float*)d_in[19]};
    const float* Alog[2] = {(const float*)d_in[12], (const float*)d_in[20]};
    const float* Dp[2]   = {(const float*)d_in[13], (const float*)d_in[21]};
    const float* gn[2]   = {(const float*)d_in[14], (const float*)d_in[22]};
    const float* Wout[2] = {(const float*)d_in[15], (const float*)d_in[23]};
    float* out = (float*)d_out;

    float *p_t, *p_nx, *p_zx, *p_y, *p_o;
    cudaGetSymbolAddress((void**)&p_t, g_t);
    cudaGetSymbolAddress((void**)&p_nx, g_nx);
    cudaGetSymbolAddress((void**)&p_zx, g_zx);
    cudaGetSymbolAddress((void**)&p_y, g_y);
    cudaGetSymbolAddress((void**)&p_o, g_o);

    const int smem64 = (2 * kAStage + 2 * 32 * 72) * 4;    // 36864
    cudaFuncSetAttribute(k_gemm_tc, cudaFuncAttributeMaxDynamicSharedMemorySize, smem64);
    cudaFuncSetAttribute(k_attn, cudaFuncAttributeMaxDynamicSharedMemorySize, kAttnSmemBytes);

    // stem: fused patchify + GEMM + bias + pos
    {
        dim3 g(kD / 64, kTOK / 64);
        k_gemm_patch<<<g, 256>>>(x, patch_w, patch_b, pos, p_t);
    }

    for (int i = 0; i < 2; i++) {
        if (i == 0)
            k_resnorm<<<kTOK / 8, 256>>>(p_t, p_o, p_o, norms_w, p_nx, 0);
        else
            k_resnorm<<<kTOK / 8, 256>>>(p_t, p_o, p_o + kTOK * kD, norms_w + kD, p_nx, 1);
        {
            dim3 g((kP + 63) / 64, kTOK / 64, 2);
            k_gemm_tc<<<g, 256, smem64>>>(p_nx, Win[0] + i * kD * kP, Win[1] + i * kD * kP,
                                          p_zx, kTOK, kP, kD, 0, (long)kTOK * kP);
        }
        {
            dim3 g(kB, kH, 2);
            k_attn<<<g, 512, kAttnSmemBytes>>>(p_zx,
                                    cw[0] + i * kCDIM * 4, cw[1] + i * kCDIM * 4,
                                    cb[0] + i * kCDIM, cb[1] + i * kCDIM,
                                    dtb[0] + i * kH, dtb[1] + i * kH,
                                    Alog[0] + i * kH, Alog[1] + i * kH,
                                    Dp[0] + i * kH, Dp[1] + i * kH, p_y);
        }
        k_gate_norm2<<<2 * kTOK / 8, 256>>>(p_zx, gn[0] + i * kDIN, gn[1] + i * kDIN, p_y);
        {
            dim3 g(kD / 64, kTOK / 64, 2);
            k_gemm_tc<<<g, 256, smem64>>>(p_y, Wout[0] + i * kDIN * kD, Wout[1] + i * kDIN * kD,
                                          p_o, kTOK, kD, kDIN, (long)kTOK * kDIN, (long)kTOK * kD);
        }
    }

    // final residual + norm, then fused mean+head
    k_resnorm<<<kTOK / 8, 256>>>(p_t, p_o, p_o + kTOK * kD, final_w, p_nx, 1);
    k_meanhead<<<dim3(kB, 5), 256>>>(p_nx, head_w, head_b, out);
}

// round 16
// speedup vs baseline: 1.0258x; 1.0258x over previous
#include <cuda_runtime.h>
#include <math.h>

// ---------------- problem constants ----------------
constexpr int kB    = 16;
constexpr int kL    = 64;
constexpr int kD    = 256;
constexpr int kDIN  = 512;
constexpr int kH    = 8;
constexpr int kDH   = 64;
constexpr int kN    = 64;
constexpr int kCDIM = 640;
constexpr int kP    = 1160;
constexpr int kPF   = 768;
constexpr int kCLS  = 1000;
constexpr float kEPS = 1e-6f;
constexpr int kTOK  = kB * kL;  // 1024

// GEMM smem geometry (floats)
constexpr int kAStride = 36;
constexpr int kAStage  = 64 * kAStride;      // 2304
constexpr int kBBase   = 2 * kAStage;        // 4608

// attn kernel smem layout (floats) — no staging buffer
constexpr int aXT  = 0;          // X transposed [p][s'] 64*68
constexpr int aBm  = 4352;       // B [s'][n] 64*68
constexpr int aCm  = 8704;       // C [s][n] 64*68; reused as W [s][s']
constexpr int aDT  = 13056;      // 64
constexpr int aCUM = 13120;      // 64
constexpr int kAttnSmemBytes = 13184 * 4;    // 52736

// ---------------- scratch ----------------
__device__ float g_t[kTOK*kD];
__device__ float g_nx[kTOK*kD];
__device__ float g_zx[2][kTOK*kP];
__device__ float g_y[2][kTOK*kDIN];
__device__ float g_o[2][kTOK*kD];

// ---------------- helpers ----------------
__device__ __forceinline__ int snake_src(int l) {
    int r = l >> 3, c = l & 7;
    return r * 8 + ((r & 1) ? (7 - c) : c);
}

__device__ __forceinline__ float warp_sum(float v) {
    #pragma unroll
    for (int o = 16; o > 0; o >>= 1) v += __shfl_xor_sync(0xffffffffu, v, o);
    return v;
}

__device__ __forceinline__ float siluf(float x) {
    return x / (1.f + expf(-x));
}

__device__ __forceinline__ unsigned f2tf32(float f) {
    unsigned r;
    asm("cvt.rna.tf32.f32 %0, %1;" : "=r"(r) : "f"(f));
    return r;
}

__device__ __forceinline__ void cpa16(float* dst, const float* src) {
    unsigned d = (unsigned)__cvta_generic_to_shared(dst);
    asm volatile("cp.async.cg.shared.global [%0], [%1], 16;" :: "r"(d), "l"(src));
}

__device__ __forceinline__ void mma_tf32(float c[4], const unsigned a[4],
                                         unsigned b0, unsigned b1) {
    asm volatile(
        "mma.sync.aligned.m16n8k8.row.col.f32.tf32.tf32.f32 "
        "{%0,%1,%2,%3}, {%4,%5,%6,%7}, {%8,%9}, {%0,%1,%2,%3};"
        : "+f"(c[0]), "+f"(c[1]), "+f"(c[2]), "+f"(c[3])
        : "r"(a[0]), "r"(a[1]), "r"(a[2]), "r"(a[3]), "r"(b0), "r"(b1));
}

// ---------------- kernels ----------------

// ---- patch GEMM: 64x64 tiles (fused patchify + transpose-B + bias + pos) ----
__global__ void __launch_bounds__(256) k_gemm_patch(
        const float* __restrict__ x, const float* __restrict__ Bw,
        const float* __restrict__ pb, const float* __restrict__ pos,
        float* __restrict__ C) {
    __shared__ unsigned As[16][72];
    __shared__ unsigned Bs[16][72];
    int tid = threadIdx.x;
    int lane = tid & 31, warp = tid >> 5;
    int lg = lane >> 2, lt = lane & 3;
    int wm = (warp >> 2) * 32;
    int wn = (warp & 3) * 16;
    int m0 = blockIdx.y * 64, n0 = blockIdx.x * 64;

    float c[2][2][4];
    #pragma unroll
    for (int a = 0; a < 2; a++)
        #pragma unroll
        for (int b = 0; b < 2; b++)
            #pragma unroll
            for (int d = 0; d < 4; d++) c[a][b][d] = 0.f;

    int am = tid >> 2;
    int ak = (tid & 3) * 4;
    int bk = tid >> 4;
    int bn = (tid & 15) * 4;

    int m = m0 + am;
    int bimg = m >> 6, l = m & 63;
    int src = snake_src(l);
    int gr = src >> 3, gc = src & 7;

    for (int k0 = 0; k0 < kPF; k0 += 16) {
        {
            int f = k0 + ak;
            int ch = f >> 8, rem = f & 255;
            int pr = rem >> 4, pc = rem & 15;
            const float* ap = x + ((long)(bimg * 3 + ch) * 128 + gr * 16 + pr) * 128
                                + gc * 16 + pc;
            float4 v = *(const float4*)(ap);
            As[ak + 0][am] = f2tf32(v.x);
            As[ak + 1][am] = f2tf32(v.y);
            As[ak + 2][am] = f2tf32(v.z);
            As[ak + 3][am] = f2tf32(v.w);
        }
        {
            #pragma unroll
            for (int j = 0; j < 4; j++)
                Bs[bk][bn + j] = f2tf32(Bw[(long)(n0 + bn + j) * kPF + k0 + bk]);
        }
        __syncthreads();
        #pragma unroll
        for (int k8 = 0; k8 < 16; k8 += 8) {
            unsigned afr[2][4], bfr[2][2];
            #pragma unroll
            for (int mt = 0; mt < 2; mt++) {
                int mb = wm + mt * 16;
                afr[mt][0] = As[k8 + lt][mb + lg];
                afr[mt][1] = As[k8 + lt][mb + 8 + lg];
                afr[mt][2] = As[k8 + lt + 4][mb + lg];
                afr[mt][3] = As[k8 + lt + 4][mb + 8 + lg];
            }
            #pragma unroll
            for (int nt = 0; nt < 2; nt++) {
                bfr[nt][0] = Bs[k8 + lt][wn + nt * 8 + lg];
                bfr[nt][1] = Bs[k8 + lt + 4][wn + nt * 8 + lg];
            }
            #pragma unroll
            for (int mt = 0; mt < 2; mt++)
                #pragma unroll
                for (int nt = 0; nt < 2; nt++)
                    mma_tf32(c[mt][nt], afr[mt], bfr[nt][0], bfr[nt][1]);
        }
        __syncthreads();
    }

    #pragma unroll
    for (int mt = 0; mt < 2; mt++) {
        int r0 = m0 + wm + mt * 16 + lg;
        int l0 = r0 & 63, l8 = (r0 + 8) & 63;
        int s0 = snake_src(l0) * kD, s8 = snake_src(l8) * kD;
        #pragma unroll
        for (int nt = 0; nt < 2; nt++) {
            int gn = n0 + wn + nt * 8 + 2 * lt;
            C[(long)r0 * kD + gn]           = c[mt][nt][0] + pb[gn] + pos[s0 + gn];
            C[(long)r0 * kD + gn + 1]       = c[mt][nt][1] + pb[gn + 1] + pos[s0 + gn + 1];
            C[(long)(r0 + 8) * kD + gn]     = c[mt][nt][2] + pb[gn] + pos[s8 + gn];
            C[(long)(r0 + 8) * kD + gn + 1] = c[mt][nt][3] + pb[gn + 1] + pos[s8 + gn + 1];
        }
    }
}

// ---- TF32 GEMM, cp.async double-buffered, K-step 32, M-tile 64, N-tile 64 ----
__global__ void __launch_bounds__(256) k_gemm_tc(
        const float* __restrict__ Abase,
        const float* __restrict__ B0, const float* __restrict__ B1,
        float* __restrict__ Cbase,
        int M, int N, int K, long sA, long sC) {
    extern __shared__ float smem[];
    constexpr int BStride = 72;
    constexpr int BStage = 32 * BStride;
    int z = blockIdx.z;
    const float* A = Abase + (long)z * sA;
    const float* B = z ? B1 : B0;
    float* C = Cbase + (long)z * sC;
    int tid = threadIdx.x;
    int lane = tid & 31, warp = tid >> 5;
    int lg = lane >> 2, lt = lane & 3;
    int wm = (warp >> 2) * 32;
    int wn = (warp & 3) * 16;
    int m0 = blockIdx.y * 64, n0 = blockIdx.x * 64;

    float c[2][2][4];
    #pragma unroll
    for (int a = 0; a < 2; a++)
        #pragma unroll
        for (int b = 0; b < 2; b++)
            #pragma unroll
            for (int d = 0; d < 4; d++) c[a][b][d] = 0.f;

    int am = tid >> 2, ak = (tid & 3) * 8;
    int bk = tid >> 3, bn = (tid & 7) * 8;

    if (n0 + 64 > N) {
        for (int i = tid; i < 2 * BStage; i += 256) smem[kBBase + i] = 0.f;
        __syncthreads();
    }

    int nIters = K >> 5;

    {
        const float* ap = A + (long)(m0 + am) * K + ak;
        float* ad = &smem[am * kAStride + ak];
        cpa16(ad, ap); cpa16(ad + 4, ap + 4);
        const float* bp = B + (long)bk * N + n0 + bn;
        float* bd = &smem[kBBase + bk * BStride + bn];
        if (n0 + bn < N) cpa16(bd, bp);
        if (n0 + bn + 4 < N) cpa16(bd + 4, bp + 4);
        asm volatile("cp.async.commit_group;");
    }

    for (int it = 0; it < nIters; it++) {
        if (it + 1 < nIters) {
            int k0 = (it + 1) << 5;
            int st = (it + 1) & 1;
            const float* ap = A + (long)(m0 + am) * K + k0 + ak;
            float* ad = &smem[st * kAStage + am * kAStride + ak];
            cpa16(ad, ap); cpa16(ad + 4, ap + 4);
            const float* bp = B + (long)(k0 + bk) * N + n0 + bn;
            float* bd = &smem[kBBase + st * BStage + bk * BStride + bn];
            if (n0 + bn < N) cpa16(bd, bp);
            if (n0 + bn + 4 < N) cpa16(bd + 4, bp + 4);
            asm volatile("cp.async.commit_group;");
            asm volatile("cp.async.wait_group 1;");
        } else {
            asm volatile("cp.async.wait_group 0;");
        }
        __syncthreads();

        const float* Ab = &smem[(it & 1) * kAStage];
        const float* Bb = &smem[kBBase + (it & 1) * BStage];
        #pragma unroll
        for (int k8 = 0; k8 < 32; k8 += 8) {
            unsigned afr[2][4], bfr[2][2];
            #pragma unroll
            for (int mt = 0; mt < 2; mt++) {
                int mb = wm + mt * 16;
                afr[mt][0] = f2tf32(Ab[(mb + lg) * kAStride + k8 + lt]);
                afr[mt][1] = f2tf32(Ab[(mb + 8 + lg) * kAStride + k8 + lt]);
                afr[mt][2] = f2tf32(Ab[(mb + lg) * kAStride + k8 + lt + 4]);
                afr[mt][3] = f2tf32(Ab[(mb + 8 + lg) * kAStride + k8 + lt + 4]);
            }
            #pragma unroll
            for (int nt = 0; nt < 2; nt++) {
                bfr[nt][0] = f2tf32(Bb[(k8 + lt) * BStride + wn + nt * 8 + lg]);
                bfr[nt][1] = f2tf32(Bb[(k8 + lt + 4) * BStride + wn + nt * 8 + lg]);
            }
            #pragma unroll
            for (int mt = 0; mt < 2; mt++)
                #pragma unroll
                for (int nt = 0; nt < 2; nt++)
                    mma_tf32(c[mt][nt], afr[mt], bfr[nt][0], bfr[nt][1]);
        }
        __syncthreads();
    }

    #pragma unroll
    for (int mt = 0; mt < 2; mt++) {
        int r0 = m0 + wm + mt * 16 + lg;
        #pragma unroll
        for (int nt = 0; nt < 2; nt++) {
            int gn = n0 + wn + nt * 8 + 2 * lt;
            if (gn < N) {
                C[(long)r0 * N + gn] = c[mt][nt][0];
                C[(long)(r0 + 8) * N + gn] = c[mt][nt][2];
                if (gn + 1 < N) {
                    C[(long)r0 * N + gn + 1] = c[mt][nt][1];
                    C[(long)(r0 + 8) * N + gn + 1] = c[mt][nt][3];
                }
            }
        }
    }
}

// ---- fused residual + rmsnorm; warp-per-row (8 rows / 256-thread block) ----
__global__ void __launch_bounds__(256) k_resnorm(
        float* __restrict__ t, const float* __restrict__ o0,
        const float* __restrict__ o1, const float* __restrict__ w,
        float* __restrict__ nx, int addRes) {
    int warp = threadIdx.x >> 5, lane = threadIdx.x & 31;
    int row = blockIdx.x * 8 + warp;
    long base = (long)row * kD;
    int d0 = lane * 4, d1 = d0 + 128;
    float4 v0 = *(float4*)&t[base + d0];
    float4 v1 = *(float4*)&t[base + d1];
    if (addRes) {
        float4 a0 = *(const float4*)&o0[base + d0];
        float4 a1 = *(const float4*)&o0[base + d1];
        float4 b0 = *(const float4*)&o1[base + d0];
        float4 b1 = *(const float4*)&o1[base + d1];
        v0.x += 0.5f * (a0.x + b0.x); v0.y += 0.5f * (a0.y + b0.y);
        v0.z += 0.5f * (a0.z + b0.z); v0.w += 0.5f * (a0.w + b0.w);
        v1.x += 0.5f * (a1.x + b1.x); v1.y += 0.5f * (a1.y + b1.y);
        v1.z += 0.5f * (a1.z + b1.z); v1.w += 0.5f * (a1.w + b1.w);
        *(float4*)&t[base + d0] = v0;
        *(float4*)&t[base + d1] = v1;
    }
    float ss = v0.x * v0.x + v0.y * v0.y + v0.z * v0.z + v0.w * v0.w
             + v1.x * v1.x + v1.y * v1.y + v1.z * v1.z + v1.w * v1.w;
    ss = warp_sum(ss);
    float sc = rsqrtf(ss * (1.f / kD) + kEPS);
    float4 w0 = *(const float4*)&w[d0];
    float4 w1 = *(const float4*)&w[d1];
    float4 r0 = make_float4(v0.x * sc * w0.x, v0.y * sc * w0.y,
                            v0.z * sc * w0.z, v0.w * sc * w0.w);
    float4 r1 = make_float4(v1.x * sc * w1.x, v1.y * sc * w1.y,
                            v1.z * sc * w1.z, v1.w * sc * w1.w);
    *(float4*)&nx[base + d0] = r0;
    *(float4*)&nx[base + d1] = r1;
}

// ---- dual-form scan on tensor cores: direct-global strip-conv + dt + MMA ----
// grid (kB, kH, 2), 512 threads; smem 52.7 KB; single barrier before MMA.
__global__ void __launch_bounds__(512) k_attn(
        const float* __restrict__ zxbase,
        const float* __restrict__ cw0, const float* __restrict__ cw1,
        const float* __restrict__ cb0, const float* __restrict__ cb1,
        const float* __restrict__ dtb0, const float* __restrict__ dtb1,
        const float* __restrict__ Alog0, const float* __restrict__ Alog1,
        const float* __restrict__ Dp0, const float* __restrict__ Dp1,
        float* __restrict__ ybase) {
    extern __shared__ float sm[];
    int b = blockIdx.x, h = blockIdx.y, dir = blockIdx.z;
    const float* zx = zxbase + (long)dir * kTOK * kP;
    float* y        = ybase  + (long)dir * kTOK * kDIN;
    const float* cw  = dir ? cw1 : cw0;
    const float* cb  = dir ? cb1 : cb0;
    float a = -expf((dir ? Alog1 : Alog0)[h]);
    float dpar = (dir ? Dp1 : Dp0)[h];
    float dtbv = (dir ? dtb1 : dtb0)[h];
    int tid = threadIdx.x;

    // warp 0: dt softplus + inclusive cumsum, fully in-warp (no barrier needed
    // between load and scan).
    if (tid < 32) {
        int s0 = 2 * tid, s1 = 2 * tid + 1;
        int tok0 = dir ? (kL - 1 - s0) : s0;
        int tok1 = dir ? (kL - 1 - s1) : s1;
        float v0 = zx[(long)(b * kL + tok0) * kP + 2 * kDIN + 2 * kN + h] + dtbv;
        float v1 = zx[(long)(b * kL + tok1) * kP + 2 * kDIN + 2 * kN + h] + dtbv;
        float d0 = (v0 > 20.f) ? v0 : log1pf(expf(v0));
        float d1 = (v1 > 20.f) ? v1 : log1pf(expf(v1));
        sm[aDT + s0] = d0;
        sm[aDT + s1] = d1;
        float p = d0 + d1;
        #pragma unroll
        for (int o = 1; o < 32; o <<= 1) {
            float t = __shfl_up_sync(0xffffffffu, p, o);
            if (tid >= o) p += t;
        }
        sm[aCUM + s0] = p - d1;
        sm[aCUM + s1] = p;
    }

    // strip conv, reading zx directly (coalesced across cc for each s).
    // 3 segments x (64 ch x 8 strips) tasks; 512 threads per segment.
    {
        int cc = tid & 63, strip = tid >> 6;
        int s0 = strip * 8;
        #pragma unroll
        for (int seg = 0; seg < 3; seg++) {
            int off = (seg == 0) ? h * kDH : (seg == 1) ? kDIN : kDIN + kN;
            const float* src = zx + kDIN + off + cc;
            int ch = off + cc;
            float w0 = cw[ch * 4 + 0], w1 = cw[ch * 4 + 1];
            float w2 = cw[ch * 4 + 2], w3 = cw[ch * 4 + 3];
            float bias = cb[ch];
            // preload 8 values + 3 halo (registers; independent loads)
            float vals[8];
            #pragma unroll
            for (int j = 0; j < 8; j++) {
                int s = s0 + j;
                int tok = dir ? (kL - 1 - s) : s;
                vals[j] = src[(long)(b * kL + tok) * kP];
            }
            float p1 = 0.f, p2 = 0.f, p3 = 0.f;
            if (s0 >= 1) { int tok = dir ? (kL - s0) : (s0 - 1);     p1 = src[(long)(b * kL + tok) * kP]; }
            if (s0 >= 2) { int tok = dir ? (kL + 1 - s0) : (s0 - 2); p2 = src[(long)(b * kL + tok) * kP]; }
            if (s0 >= 3) { int tok = dir ? (kL + 2 - s0) : (s0 - 3); p3 = src[(long)(b * kL + tok) * kP]; }
            #pragma unroll
            for (int j = 0; j < 8; j++) {
                int s = s0 + j;
                float v = vals[j];
                float acc = bias + w0 * p3 + w1 * p2 + w2 * p1 + w3 * v;
                float o = siluf(acc);
                if (seg == 0) sm[aXT + cc * 68 + s] = o;
                else if (seg == 1) sm[aBm + s * 68 + cc] = o;
                else sm[aCm + s * 68 + cc] = o;
                p3 = p2; p2 = p1; p1 = v;
            }
        }
    }
    __syncthreads();

    int warp = tid >> 5, lane = tid & 31;
    int lg = lane >> 2, lt = lane & 3;
    int mw = (warp >> 2) * 16;       // s rows
    int nw = (warp & 3) * 16;        // sp / p cols

    // ---- phase 1: G = C @ B^T via tf32 MMA ----
    float g[2][4];
    #pragma unroll
    for (int nt = 0; nt < 2; nt++)
        #pragma unroll
        for (int d = 0; d < 4; d++) g[nt][d] = 0.f;
    #pragma unroll
    for (int k0 = 0; k0 < 64; k0 += 8) {
        unsigned af[4];
        af[0] = f2tf32(sm[aCm + (mw + lg) * 68 + k0 + lt]);
        af[1] = f2tf32(sm[aCm + (mw + 8 + lg) * 68 + k0 + lt]);
        af[2] = f2tf32(sm[aCm + (mw + lg) * 68 + k0 + lt + 4]);
        af[3] = f2tf32(sm[aCm + (mw + 8 + lg) * 68 + k0 + lt + 4]);
        #pragma unroll
        for (int nt = 0; nt < 2; nt++) {
            unsigned b0 = f2tf32(sm[aBm + (nw + nt * 8 + lg) * 68 + k0 + lt]);
            unsigned b1 = f2tf32(sm[aBm + (nw + nt * 8 + lg) * 68 + k0 + lt + 4]);
            mma_tf32(g[nt], af, b0, b1);
        }
    }
    __syncthreads();   // all C/B reads done; aCm can be overwritten with W

    // mask + store W into aCm [s][sp]
    {
        int s0 = mw + lg, s8 = mw + 8 + lg;
        float cum0 = sm[aCUM + s0], cum8 = sm[aCUM + s8];
        #pragma unroll
        for (int nt = 0; nt < 2; nt++) {
            int sp = nw + nt * 8 + 2 * lt;
            float csp0 = sm[aCUM + sp], csp1 = sm[aCUM + sp + 1];
            float dt0 = sm[aDT + sp], dt1 = sm[aDT + sp + 1];
            sm[aCm + s0 * 68 + sp]     = (sp     <= s0) ? g[nt][0] * __expf(a * (cum0 - csp0)) * dt0 : 0.f;
            sm[aCm + s0 * 68 + sp + 1] = (sp + 1 <= s0) ? g[nt][1] * __expf(a * (cum0 - csp1)) * dt1 : 0.f;
            sm[aCm + s8 * 68 + sp]     = (sp     <= s8) ? g[nt][2] * __expf(a * (cum8 - csp0)) * dt0 : 0.f;
            sm[aCm + s8 * 68 + sp + 1] = (sp + 1 <= s8) ? g[nt][3] * __expf(a * (cum8 - csp1)) * dt1 : 0.f;
        }
    }
    __syncthreads();

    // ---- phase 2: Y = W @ X via tf32 MMA (A = W[s][sp], B-op = XT[p][sp]) ----
    float yv[2][4];
    #pragma unroll
    for (int nt = 0; nt < 2; nt++)
        #pragma unroll
        for (int d = 0; d < 4; d++) yv[nt][d] = 0.f;
    #pragma unroll
    for (int k0 = 0; k0 < 64; k0 += 8) {
        unsigned af[4];
        af[0] = f2tf32(sm[aCm + (mw + lg) * 68 + k0 + lt]);
        af[1] = f2tf32(sm[aCm + (mw + 8 + lg) * 68 + k0 + lt]);
        af[2] = f2tf32(sm[aCm + (mw + lg) * 68 + k0 + lt + 4]);
        af[3] = f2tf32(sm[aCm + (mw + 8 + lg) * 68 + k0 + lt + 4]);
        #pragma unroll
        for (int nt = 0; nt < 2; nt++) {
            unsigned b0 = f2tf32(sm[aXT + (nw + nt * 8 + lg) * 68 + k0 + lt]);
            unsigned b1 = f2tf32(sm[aXT + (nw + nt * 8 + lg) * 68 + k0 + lt + 4]);
            mma_tf32(yv[nt], af, b0, b1);
        }
    }

    // epilogue: + D*x, write token-order (float2 pairs)
    {
        int s0 = mw + lg, s8 = mw + 8 + lg;
        int tok0 = dir ? (kL - 1 - s0) : s0;
        int tok8 = dir ? (kL - 1 - s8) : s8;
        #pragma unroll
        for (int nt = 0; nt < 2; nt++) {
            int p0 = nw + nt * 8 + 2 * lt;
            float x00 = sm[aXT + p0 * 68 + s0];
            float x01 = sm[aXT + (p0 + 1) * 68 + s0];
            float x80 = sm[aXT + p0 * 68 + s8];
            float x81 = sm[aXT + (p0 + 1) * 68 + s8];
            float2 o0 = make_float2(yv[nt][0] + dpar * x00, yv[nt][1] + dpar * x01);
            float2 o8 = make_float2(yv[nt][2] + dpar * x80, yv[nt][3] + dpar * x81);
            *(float2*)&y[(long)(b * kL + tok0) * kDIN + h * kDH + p0] = o0;
            *(float2*)&y[(long)(b * kL + tok8) * kDIN + h * kDH + p0] = o8;
        }
    }
}

// ---- gate + rmsnorm over DIN; warp-per-row (8 rows / block), both dirs ----
__global__ void __launch_bounds__(256) k_gate_norm2(
        const float* __restrict__ zxbase,
        const float* __restrict__ gn0, const float* __restrict__ gn1,
        float* __restrict__ ybase) {
    int warp = threadIdx.x >> 5, lane = threadIdx.x & 31;
    int row = blockIdx.x * 8 + warp;          // 0..2*kTOK-1
    const float* gn = (row >= kTOK) ? gn1 : gn0;
    const float* zrow = zxbase + (long)row * kP;
    float* yrow = ybase + (long)row * kDIN;
    float4 v[4];
    float ss = 0.f;
    #pragma unroll
    for (int q = 0; q < 4; q++) {
        int d = lane * 4 + q * 128;
        float4 yv = *(const float4*)&yrow[d];
        float4 zv = *(const float4*)&zrow[d];
        v[q].x = yv.x * siluf(zv.x);
        v[q].y = yv.y * siluf(zv.y);
        v[q].z = yv.z * siluf(zv.z);
        v[q].w = yv.w * siluf(zv.w);
        ss += v[q].x * v[q].x + v[q].y * v[q].y + v[q].z * v[q].z + v[q].w * v[q].w;
    }
    ss = warp_sum(ss);
    float sc = rsqrtf(ss * (1.f / kDIN) + kEPS);
    #pragma unroll
    for (int q = 0; q < 4; q++) {
        int d = lane * 4 + q * 128;
        float4 gv = *(const float4*)&gn[d];
        float4 o = make_float4(v[q].x * sc * gv.x, v[q].y * sc * gv.y,
                               v[q].z * sc * gv.z, v[q].w * sc * gv.w);
        *(float4*)&yrow[d] = o;
    }
}

// ---- fused mean-pool + classifier head; grid (kB, 5), 200 classes/block ----
__global__ void k_meanhead(const float* __restrict__ nx, const float* __restrict__ hw,
                           const float* __restrict__ hb, float* __restrict__ out) {
    int b = blockIdx.x;
    int c0 = blockIdx.y * 200;
    int t = threadIdx.x;
    __shared__ float pool[kD];
    float s = 0.f;
    #pragma unroll 8
    for (int l = 0; l < kL; l++) s += nx[(long)(b * kL + l) * kD + t];
    pool[t] = s * (1.f / kL);
    __syncthreads();
    for (int n = c0 + t; n < c0 + 200 && n < kCLS; n += 256) {
        float acc = hb[n];
        #pragma unroll 8
        for (int k = 0; k < kD; k++) acc += pool[k] * hw[(long)k * kCLS + n];
        out[(long)b * kCLS + n] = acc;
    }
}

// ---------------- launch ----------------
extern "C" void kernel_launch(void* const* d_in, const int* in_sizes, int n_in,
                              void* d_out, int out_size) {
    const float* x       = (const float*)d_in[0];
    const float* patch_w = (const float*)d_in[1];
    const float* patch_b = (const float*)d_in[2];
    const float* pos     = (const float*)d_in[3];
    const float* norms_w = (const float*)d_in[4];
    const float* final_w = (const float*)d_in[5];
    const float* head_w  = (const float*)d_in[6];
    const float* head_b  = (const float*)d_in[7];
    const float* Win[2]  = {(const float*)d_in[8],  (const float*)d_in[16]};
    const float* cw[2]   = {(const float*)d_in[9],  (const float*)d_in[17]};
    const float* cb[2]   = {(const float*)d_in[10], (const float*)d_in[18]};
    const float* dtb[2]  = {(const float*)d_in[11], (const float*)d_in[19]};
    const float* Alog[2] = {(const float*)d_in[12], (const float*)d_in[20]};
    const float* Dp[2]   = {(const float*)d_in[13], (const float*)d_in[21]};
    const float* gn[2]   = {(const float*)d_in[14], (const float*)d_in[22]};
    const float* Wout[2] = {(const float*)d_in[15], (const float*)d_in[23]};
    float* out = (float*)d_out;

    float *p_t, *p_nx, *p_zx, *p_y, *p_o;
    cudaGetSymbolAddress((void**)&p_t, g_t);
    cudaGetSymbolAddress((void**)&p_nx, g_nx);
    cudaGetSymbolAddress((void**)&p_zx, g_zx);
    cudaGetSymbolAddress((void**)&p_y, g_y);
    cudaGetSymbolAddress((void**)&p_o, g_o);

    const int smem64 = (2 * kAStage + 2 * 32 * 72) * 4;    // 36864
    cudaFuncSetAttribute(k_gemm_tc, cudaFuncAttributeMaxDynamicSharedMemorySize, smem64);
    cudaFuncSetAttribute(k_attn, cudaFuncAttributeMaxDynamicSharedMemorySize, kAttnSmemBytes);

    // stem: fused patchify + GEMM + bias + pos
    {
        dim3 g(kD / 64, kTOK / 64);
        k_gemm_patch<<<g, 256>>>(x, patch_w, patch_b, pos, p_t);
    }

    for (int i = 0; i < 2; i++) {
        if (i == 0)
            k_resnorm<<<kTOK / 8, 256>>>(p_t, p_o, p_o, norms_w, p_nx, 0);
        else
            k_resnorm<<<kTOK / 8, 256>>>(p_t, p_o, p_o + kTOK * kD, norms_w + kD, p_nx, 1);
        {
            dim3 g((kP + 63) / 64, kTOK / 64, 2);
            k_gemm_tc<<<g, 256, smem64>>>(p_nx, Win[0] + i * kD * kP, Win[1] + i * kD * kP,
                                          p_zx, kTOK, kP, kD, 0, (long)kTOK * kP);
        }
        {
            dim3 g(kB, kH, 2);
            k_attn<<<g, 512, kAttnSmemBytes>>>(p_zx,
                                    cw[0] + i * kCDIM * 4, cw[1] + i * kCDIM * 4,
                                    cb[0] + i * kCDIM, cb[1] + i * kCDIM,
                                    dtb[0] + i * kH, dtb[1] + i * kH,
                                    Alog[0] + i * kH, Alog[1] + i * kH,
                                    Dp[0] + i * kH, Dp[1] + i * kH, p_y);
        }
        k_gate_norm2<<<2 * kTOK / 8, 256>>>(p_zx, gn[0] + i * kDIN, gn[1] + i * kDIN, p_y);
        {
            dim3 g(kD / 64, kTOK / 64, 2);
            k_gemm_tc<<<g, 256, smem64>>>(p_y, Wout[0] + i * kDIN * kD, Wout[1] + i * kDIN * kD,
                                          p_o, kTOK, kD, kDIN, (long)kTOK * kDIN, (long)kTOK * kD);
        }
    }

    // final residual + norm, then fused mean+head
    k_resnorm<<<kTOK / 8, 256>>>(p_t, p_o, p_o + kTOK * kD, final_w, p_nx, 1);
    k_meanhead<<<dim3(kB, 5), 256>>>(p_nx, head_w, head_b, out);
}